// round 14
// baseline (speedup 1.0000x reference)
#include <cuda_runtime.h>

// LSTM B=1024 T=512 F=40 H=50 + MLP head. Round 13: split design (R10 base,
// measured kernel2=650us standalone) with SMSP-balanced warps.
//
// Defect fixed: 224-thread blocks (7 warps) and tid<200 compute masks put
// 2x the work on SMSPs 0-2 vs 3 and idle whole warps; barriers make every
// step wait for the most-loaded SMSP. Now compute lanes are `lane < 25` in
// EVERY warp (8 warps x 25 = 200 gates) -> identical per-warp streams,
// all 4 SMSPs balanced.
//
// Kernel 1: xg[tok][j] = (bih+bhh)[j] + W_ih[j].x[tok]; 8192 CTAs x 128 thr,
//   4 warps x 25 compute lanes (2 gates each), 4-token unroll, coalesced
//   float2 stores. Scratch g_xg (420 MB, .bss - validated in R10/R12).
// Kernel 2: recurrence, K=50 only. 256 CTAs x 256 thr, RR=4 rows, 2 CTA/SM.
//   Warp w lane l<25 owns gate j=25w+l: W_hh row in 26 packed f32x2 regs,
//   gates for 4 rows vs broadcast ld.shared.v2.u64 of h; xg prefetched one
//   step ahead (coalesced LDG). Two barriers/step; c register-resident.

#define BB   1024
#define TT   512
#define FF   40
#define HH   50
#define GG   200
#define RR   4
#define KZ   52           // padded h vector (50 + 2) = 13 ull2, 16B-aligned
#define NTH2 256
#define NGRID2 256        // 1024 / RR

#define NT1  128
#define TPC  64
#define NGRID1 ((BB * TT) / TPC)   // 8192

__device__ float g_xg[(size_t)BB * TT * GG];   // 420 MB scratch (.bss)

__device__ __forceinline__ unsigned long long pk2(float lo, float hi) {
    unsigned long long r;
    asm("mov.b64 %0, {%1, %2};" : "=l"(r) : "f"(lo), "f"(hi));
    return r;
}
__device__ __forceinline__ void upk2(unsigned long long v, float& lo, float& hi) {
    asm("mov.b64 {%0, %1}, %2;" : "=f"(lo), "=f"(hi) : "l"(v));
}
__device__ __forceinline__ unsigned long long f2fma(unsigned long long a,
                                                   unsigned long long b,
                                                   unsigned long long c) {
    unsigned long long d;
    asm("fma.rn.f32x2 %0, %1, %2, %3;" : "=l"(d) : "l"(a), "l"(b), "l"(c));
    return d;
}
__device__ __forceinline__ float tanh_f(float x) {
    float y;
    asm("tanh.approx.f32 %0, %1;" : "=f"(y) : "f"(x));
    return y;
}
__device__ __forceinline__ float sig_f(float x) {
    return fmaf(0.5f, tanh_f(0.5f * x), 0.5f);
}

// ================= kernel 1: xg precompute =================
__global__ __launch_bounds__(NT1, 4)
void xg_kernel(const float* __restrict__ x,   const float* __restrict__ Wih,
               const float* __restrict__ bih, const float* __restrict__ bhh)
{
    __shared__ __align__(16) float sX[TPC * FF];   // 10 KB token tile

    const int tid  = threadIdx.x;
    const int wid  = tid >> 5;
    const int lane = tid & 31;
    const long tok0 = (long)blockIdx.x * TPC;

    // stage x tile (contiguous TPC*40 floats), all 128 threads
    const float4* __restrict__ src = (const float4*)(x + tok0 * FF);
    #pragma unroll
    for (int i = tid; i < TPC * FF / 4; i += NT1)
        ((float4*)sX)[i] = src[i];

    // compute lanes: lane<25 in every warp; jj = wid*25+lane in 0..99
    const bool comp = (lane < 25);
    const int jj = wid * 25 + lane;
    const int j0 = 2 * jj;                          // gates j0, j0+1

    unsigned long long w[40];
    float bsA = 0.f, bsB = 0.f;
    #pragma unroll
    for (int k = 0; k < 20; ++k) {
        w[k]      = comp ? pk2(Wih[j0 * FF + 2 * k],       Wih[j0 * FF + 2 * k + 1])       : 0ull;
        w[20 + k] = comp ? pk2(Wih[(j0 + 1) * FF + 2 * k], Wih[(j0 + 1) * FF + 2 * k + 1]) : 0ull;
    }
    if (comp) { bsA = bih[j0] + bhh[j0]; bsB = bih[j0 + 1] + bhh[j0 + 1]; }
    __syncthreads();

    #pragma unroll 1
    for (int tt = 0; tt < TPC; tt += 4) {           // 4 tokens per iter
        unsigned long long aA[4], aB[4];
        #pragma unroll
        for (int s = 0; s < 4; ++s) { aA[s] = pk2(bsA, 0.f); aB[s] = pk2(bsB, 0.f); }
        #pragma unroll
        for (int i = 0; i < 10; ++i) {
            unsigned long long wA0 = w[2 * i],      wA1 = w[2 * i + 1];
            unsigned long long wB0 = w[20 + 2 * i], wB1 = w[20 + 2 * i + 1];
            #pragma unroll
            for (int s = 0; s < 4; ++s) {
                ulonglong2 z = ((const ulonglong2*)(sX + (tt + s) * FF))[i];
                aA[s] = f2fma(wA0, z.x, aA[s]); aA[s] = f2fma(wA1, z.y, aA[s]);
                aB[s] = f2fma(wB0, z.x, aB[s]); aB[s] = f2fma(wB1, z.y, aB[s]);
            }
        }
        if (comp) {
            #pragma unroll
            for (int s = 0; s < 4; ++s) {
                float lo, hi, vA, vB;
                upk2(aA[s], lo, hi); vA = lo + hi;
                upk2(aB[s], lo, hi); vB = lo + hi;
                *(float2*)(g_xg + (tok0 + tt + s) * GG + j0) = make_float2(vA, vB);
            }
        }
    }
}

// ================= kernel 2: recurrence (K = 50) =================
__global__ __launch_bounds__(NTH2, 2)
void lstm_kernel(const float* __restrict__ x,  const float* __restrict__ Whh,
                 const float* __restrict__ W1, const float* __restrict__ b1,
                 const float* __restrict__ W2, const float* __restrict__ b2,
                 float* __restrict__ out)
{
    __shared__ __align__(16) float sZ[RR][KZ];     // h (+2 pad) per row
    __shared__ __align__(16) float sG[RR][GG];     // pre-activation gates
    __shared__ __align__(16) float sH[RR * 10];    // head scratch

    const int tid  = threadIdx.x;
    const int wid  = tid >> 5;
    const int lane = tid & 31;
    const int b0   = blockIdx.x * RR;

    // zero h buffer (h0 = 0, pads stay 0)
    for (int i = tid; i < RR * KZ; i += NTH2) ((float*)sZ)[i] = 0.0f;

    // compute role: lane<25 in every warp -> gate j = 25*wid + lane
    const bool comp = (lane < 25);
    const int j = wid * 25 + lane;                 // 0..199 when comp

    // W_hh row j: 26 packed f32x2 (50 real + 2 zero-pad)
    unsigned long long wh[26];
    #pragma unroll
    for (int kk = 0; kk < 26; ++kk) {
        int k0 = 2 * kk, k1 = 2 * kk + 1;
        float lo = (comp && k0 < HH) ? Whh[j * HH + k0] : 0.0f;
        float hi = (comp && k1 < HH) ? Whh[j * HH + k1] : 0.0f;
        wh[kk] = pk2(lo, hi);
    }

    // cell role (cr, cu) for same thread; c0[:,0] = 1
    const int cr = j / HH;
    const int cu = j - cr * HH;
    float creg = (comp && cu == 0) ? 1.0f : 0.0f;

    // xg streams, one per row; load t=0 now
    const float* __restrict__ p0 = g_xg + ((long)(b0 + 0) * TT) * GG + j;
    const float* __restrict__ p1 = g_xg + ((long)(b0 + 1) * TT) * GG + j;
    const float* __restrict__ p2 = g_xg + ((long)(b0 + 2) * TT) * GG + j;
    const float* __restrict__ p3 = g_xg + ((long)(b0 + 3) * TT) * GG + j;
    float c0v = 0.f, c1v = 0.f, c2v = 0.f, c3v = 0.f;
    if (comp) { c0v = *p0; c1v = *p1; c2v = *p2; c3v = *p3; }
    __syncthreads();

    for (int t = 0; t < TT; ++t) {
        float n0 = 0.f, n1 = 0.f, n2 = 0.f, n3 = 0.f;
        if (comp) {
            if ((t + 1) < TT) {                    // prefetch xg[t+1]
                n0 = p0[(t + 1) * GG];
                n1 = p1[(t + 1) * GG];
                n2 = p2[(t + 1) * GG];
                n3 = p3[(t + 1) * GG];
            }
            unsigned long long a0 = pk2(c0v, 0.f), a1 = pk2(c1v, 0.f);
            unsigned long long a2 = pk2(c2v, 0.f), a3 = pk2(c3v, 0.f);
            const ulonglong2* __restrict__ zb = (const ulonglong2*)&sZ[0][0];
            #pragma unroll
            for (int i = 0; i < 13; ++i) {         // 13 ull2 per row
                ulonglong2 z0 = zb[ 0 + i];
                ulonglong2 z1 = zb[13 + i];
                ulonglong2 z2 = zb[26 + i];
                ulonglong2 z3 = zb[39 + i];
                unsigned long long wa = wh[2 * i], wb = wh[2 * i + 1];
                a0 = f2fma(wa, z0.x, a0); a0 = f2fma(wb, z0.y, a0);
                a1 = f2fma(wa, z1.x, a1); a1 = f2fma(wb, z1.y, a1);
                a2 = f2fma(wa, z2.x, a2); a2 = f2fma(wb, z2.y, a2);
                a3 = f2fma(wa, z3.x, a3); a3 = f2fma(wb, z3.y, a3);
            }
            float lo, hi;
            upk2(a0, lo, hi); sG[0][j] = lo + hi;
            upk2(a1, lo, hi); sG[1][j] = lo + hi;
            upk2(a2, lo, hi); sG[2][j] = lo + hi;
            upk2(a3, lo, hi); sG[3][j] = lo + hi;
        }
        __syncthreads();

        if (comp) {
            float gi = sG[cr][         cu];
            float gf = sG[cr][    HH + cu];
            float gc = sG[cr][2 * HH + cu];
            float go = sG[cr][3 * HH + cu];
            float si = sig_f(gi);
            float sf = sig_f(gf);
            float tg = tanh_f(gc);
            float so = sig_f(go);
            creg = fmaf(sf, creg, si * tg);
            sZ[cr][cu] = so * tanh_f(creg);
        }
        __syncthreads();

        c0v = n0; c1v = n1; c2v = n2; c3v = n3;
    }

    // ================= MLP head =================
    if (tid < RR * 10) {
        int r = tid / 10, m = tid - (tid / 10) * 10;
        float s = b1[m];
        #pragma unroll
        for (int u = 0; u < HH; ++u)
            s = fmaf(sZ[r][u], W1[m * HH + u], s);
        sH[tid] = fmaxf(s, 0.0f);
    }
    __syncthreads();

    if (tid < RR) {
        float o = b2[0];
        #pragma unroll
        for (int m = 0; m < 10; ++m)
            o = fmaf(sH[tid * 10 + m], W2[m], o);
        out[b0 + tid] = o + x[((long)(b0 + tid) * TT + (TT - 1)) * FF + 0];
    }
}

extern "C" void kernel_launch(void* const* d_in, const int* in_sizes, int n_in,
                              void* d_out, int out_size)
{
    const float* x   = (const float*)d_in[0];
    const float* Wih = (const float*)d_in[1];
    const float* Whh = (const float*)d_in[2];
    const float* bih = (const float*)d_in[3];
    const float* bhh = (const float*)d_in[4];
    const float* W1  = (const float*)d_in[5];
    const float* b1  = (const float*)d_in[6];
    const float* W2  = (const float*)d_in[7];
    const float* b2  = (const float*)d_in[8];
    float* out = (float*)d_out;

    xg_kernel<<<NGRID1, NT1>>>(x, Wih, bih, bhh);
    lstm_kernel<<<NGRID2, NTH2>>>(x, Whh, W1, b1, W2, b2, out);
}

// round 15
// speedup vs baseline: 1.3100x; 1.3100x over previous
#include <cuda_runtime.h>

// LSTM B=1024 T=512 F=40 H=50 + MLP head. Round 14: 4 independent CTAs/SM.
//
// Kernel 1 (xg precompute): exact R10 shape (measured 260us): 4096 CTAs x
//   128 thr, tid<100 computes 2 gates, 2-token unroll, W_ih rows in regs,
//   x tile in SMEM, float2 stores to g_xg (420 MB .bss scratch).
// Kernel 2 (recurrence, K=50): 512 CTAs x 128 thr (4 warps = 1/SMSP),
//   RR=2 rows/CTA, 4 CTAs/SM (launch_bounds(128,4), regs<=128).
//   lane<25 in every warp -> slot s = 25*wid+lane (0..99): gate PAIR
//   j0=2s, j0+1. Weights: 2 x 25 packed f32x2 (K=50 exact). Phase A:
//   4 accums (2 gates x 2 rows) vs broadcast LDS of h (12x LDS.128 + 1x
//   LDS.64 per row); init from prefetched xg (float2, 1 step lookahead).
//   Phase B: cell (cr=s/50, cu=s%50), MUFU activations, register c.
//   Two __syncthreads/step; 4 CTAs' independent cadences fill each
//   other's latency bubbles.

#define BB   1024
#define TT   512
#define FF   40
#define HH   50
#define GG   200
#define RR2  2
#define KZ   52           // h row stride (50 + 2 pad) -> 16B aligned
#define NTH2 128
#define NGRID2 512        // 1024 / RR2

#define NT1  128
#define TPC  128
#define NGRID1 ((BB * TT) / TPC)   // 4096

__device__ float g_xg[(size_t)BB * TT * GG];   // 420 MB scratch (.bss)

__device__ __forceinline__ unsigned long long pk2(float lo, float hi) {
    unsigned long long r;
    asm("mov.b64 %0, {%1, %2};" : "=l"(r) : "f"(lo), "f"(hi));
    return r;
}
__device__ __forceinline__ void upk2(unsigned long long v, float& lo, float& hi) {
    asm("mov.b64 {%0, %1}, %2;" : "=f"(lo), "=f"(hi) : "l"(v));
}
__device__ __forceinline__ unsigned long long f2fma(unsigned long long a,
                                                   unsigned long long b,
                                                   unsigned long long c) {
    unsigned long long d;
    asm("fma.rn.f32x2 %0, %1, %2, %3;" : "=l"(d) : "l"(a), "l"(b), "l"(c));
    return d;
}
__device__ __forceinline__ float tanh_f(float x) {
    float y;
    asm("tanh.approx.f32 %0, %1;" : "=f"(y) : "f"(x));
    return y;
}
__device__ __forceinline__ float sig_f(float x) {
    return fmaf(0.5f, tanh_f(0.5f * x), 0.5f);
}

// ================= kernel 1: xg precompute (R10 shape) =================
__global__ __launch_bounds__(NT1, 4)
void xg_kernel(const float* __restrict__ x,   const float* __restrict__ Wih,
               const float* __restrict__ bih, const float* __restrict__ bhh)
{
    __shared__ __align__(16) float sX[TPC * FF];   // 20 KB token tile

    const int tid = threadIdx.x;
    const long tok0 = (long)blockIdx.x * TPC;

    const float4* __restrict__ src = (const float4*)(x + tok0 * FF);
    #pragma unroll
    for (int i = tid; i < TPC * FF / 4; i += NT1)
        ((float4*)sX)[i] = src[i];

    const int j0 = 2 * tid;
    unsigned long long w[40];
    float bsA = 0.f, bsB = 0.f;
    if (tid < 100) {
        #pragma unroll
        for (int k = 0; k < 20; ++k)
            w[k]      = pk2(Wih[j0 * FF + 2 * k],       Wih[j0 * FF + 2 * k + 1]);
        #pragma unroll
        for (int k = 0; k < 20; ++k)
            w[20 + k] = pk2(Wih[(j0 + 1) * FF + 2 * k], Wih[(j0 + 1) * FF + 2 * k + 1]);
        bsA = bih[j0]     + bhh[j0];
        bsB = bih[j0 + 1] + bhh[j0 + 1];
    }
    __syncthreads();

    if (tid < 100) {
        #pragma unroll 1
        for (int tt = 0; tt < TPC; tt += 2) {
            const ulonglong2* __restrict__ xz0 = (const ulonglong2*)(sX + tt * FF);
            const ulonglong2* __restrict__ xz1 = (const ulonglong2*)(sX + (tt + 1) * FF);
            unsigned long long aA0 = pk2(bsA, 0.f), aB0 = pk2(bsB, 0.f);
            unsigned long long aA1 = pk2(bsA, 0.f), aB1 = pk2(bsB, 0.f);
            #pragma unroll
            for (int i = 0; i < 10; ++i) {
                ulonglong2 z0 = xz0[i];
                ulonglong2 z1 = xz1[i];
                unsigned long long wA0 = w[2 * i],      wA1 = w[2 * i + 1];
                unsigned long long wB0 = w[20 + 2 * i], wB1 = w[20 + 2 * i + 1];
                aA0 = f2fma(wA0, z0.x, aA0); aA0 = f2fma(wA1, z0.y, aA0);
                aB0 = f2fma(wB0, z0.x, aB0); aB0 = f2fma(wB1, z0.y, aB0);
                aA1 = f2fma(wA0, z1.x, aA1); aA1 = f2fma(wA1, z1.y, aA1);
                aB1 = f2fma(wB0, z1.x, aB1); aB1 = f2fma(wB1, z1.y, aB1);
            }
            float lo, hi, vA, vB;
            upk2(aA0, lo, hi); vA = lo + hi;
            upk2(aB0, lo, hi); vB = lo + hi;
            *(float2*)(g_xg + (tok0 + tt) * GG + j0)     = make_float2(vA, vB);
            upk2(aA1, lo, hi); vA = lo + hi;
            upk2(aB1, lo, hi); vB = lo + hi;
            *(float2*)(g_xg + (tok0 + tt + 1) * GG + j0) = make_float2(vA, vB);
        }
    }
}

// ================= kernel 2: recurrence (K=50, 4 CTAs/SM) =================
__global__ __launch_bounds__(NTH2, 4)
void lstm_kernel(const float* __restrict__ x,  const float* __restrict__ Whh,
                 const float* __restrict__ W1, const float* __restrict__ b1,
                 const float* __restrict__ W2, const float* __restrict__ b2,
                 float* __restrict__ out)
{
    __shared__ __align__(16) float sZ[RR2][KZ];   // h (+2 pad) per row
    __shared__ __align__(16) float sG[RR2][GG];   // pre-activation gates
    __shared__ __align__(16) float sH[RR2 * 10];  // head scratch

    const int tid  = threadIdx.x;
    const int wid  = tid >> 5;
    const int lane = tid & 31;
    const int b0   = blockIdx.x * RR2;

    for (int i = tid; i < RR2 * KZ; i += NTH2) ((float*)sZ)[i] = 0.0f;

    // compute role: slot s = 25*wid + lane (lane<25) -> gates 2s, 2s+1
    const bool comp = (lane < 25);
    const int s  = wid * 25 + lane;
    const int j0 = 2 * s;

    // W_hh rows j0 and j0+1: 25 packed f32x2 each (K=50 exact)
    unsigned long long w0[25], w1[25];
    #pragma unroll
    for (int k = 0; k < 25; ++k) {
        w0[k] = comp ? pk2(Whh[j0 * HH + 2 * k],       Whh[j0 * HH + 2 * k + 1])       : 0ull;
        w1[k] = comp ? pk2(Whh[(j0 + 1) * HH + 2 * k], Whh[(j0 + 1) * HH + 2 * k + 1]) : 0ull;
    }

    // cell role: s -> (cr = s/50, cu = s%50); c0[:,0] = 1
    const int cr = s / HH;
    const int cu = s - cr * HH;
    float creg = (comp && cu == 0) ? 1.0f : 0.0f;

    // xg streams (float2 per row), load t=0
    const float* __restrict__ pA = g_xg + ((long)(b0 + 0) * TT) * GG + j0;
    const float* __restrict__ pB = g_xg + ((long)(b0 + 1) * TT) * GG + j0;
    float2 xg0 = make_float2(0.f, 0.f), xg1 = xg0;
    if (comp) { xg0 = *(const float2*)pA; xg1 = *(const float2*)pB; }
    __syncthreads();

    for (int t = 0; t < TT; ++t) {
        float2 nx0 = make_float2(0.f, 0.f), nx1 = nx0;
        if (comp) {
            if ((t + 1) < TT) {                    // prefetch xg[t+1]
                nx0 = *(const float2*)(pA + (t + 1) * GG);
                nx1 = *(const float2*)(pB + (t + 1) * GG);
            }
            // accums: a<gate><row>
            unsigned long long a00 = pk2(xg0.x, 0.f);
            unsigned long long a10 = pk2(xg0.y, 0.f);
            unsigned long long a01 = pk2(xg1.x, 0.f);
            unsigned long long a11 = pk2(xg1.y, 0.f);
            const ulonglong2* __restrict__ z0b = (const ulonglong2*)&sZ[0][0];
            const ulonglong2* __restrict__ z1b = (const ulonglong2*)&sZ[1][0];
            #pragma unroll
            for (int i = 0; i < 12; ++i) {         // k = 0..47
                ulonglong2 z0 = z0b[i];
                ulonglong2 z1 = z1b[i];
                unsigned long long wa0 = w0[2 * i], wb0 = w0[2 * i + 1];
                unsigned long long wa1 = w1[2 * i], wb1 = w1[2 * i + 1];
                a00 = f2fma(wa0, z0.x, a00); a00 = f2fma(wb0, z0.y, a00);
                a10 = f2fma(wa1, z0.x, a10); a10 = f2fma(wb1, z0.y, a10);
                a01 = f2fma(wa0, z1.x, a01); a01 = f2fma(wb0, z1.y, a01);
                a11 = f2fma(wa1, z1.x, a11); a11 = f2fma(wb1, z1.y, a11);
            }
            {   // tail k = 48,49
                unsigned long long zt0 = *(const unsigned long long*)&sZ[0][48];
                unsigned long long zt1 = *(const unsigned long long*)&sZ[1][48];
                a00 = f2fma(w0[24], zt0, a00);
                a10 = f2fma(w1[24], zt0, a10);
                a01 = f2fma(w0[24], zt1, a01);
                a11 = f2fma(w1[24], zt1, a11);
            }
            float lo, hi, g0v, g1v;
            upk2(a00, lo, hi); g0v = lo + hi;
            upk2(a10, lo, hi); g1v = lo + hi;
            *(float2*)&sG[0][j0] = make_float2(g0v, g1v);
            upk2(a01, lo, hi); g0v = lo + hi;
            upk2(a11, lo, hi); g1v = lo + hi;
            *(float2*)&sG[1][j0] = make_float2(g0v, g1v);
        }
        __syncthreads();

        if (comp) {
            float gi = sG[cr][         cu];
            float gf = sG[cr][    HH + cu];
            float gc = sG[cr][2 * HH + cu];
            float go = sG[cr][3 * HH + cu];
            float si = sig_f(gi);
            float sf = sig_f(gf);
            float tg = tanh_f(gc);
            float so = sig_f(go);
            creg = fmaf(sf, creg, si * tg);
            sZ[cr][cu] = so * tanh_f(creg);
        }
        __syncthreads();

        xg0 = nx0; xg1 = nx1;
    }

    // ================= MLP head =================
    if (tid < RR2 * 10) {
        int r = tid / 10, m = tid - (tid / 10) * 10;
        float sacc = b1[m];
        #pragma unroll
        for (int u = 0; u < HH; ++u)
            sacc = fmaf(sZ[r][u], W1[m * HH + u], sacc);
        sH[tid] = fmaxf(sacc, 0.0f);
    }
    __syncthreads();

    if (tid < RR2) {
        float o = b2[0];
        #pragma unroll
        for (int m = 0; m < 10; ++m)
            o = fmaf(sH[tid * 10 + m], W2[m], o);
        out[b0 + tid] = o + x[((long)(b0 + tid) * TT + (TT - 1)) * FF + 0];
    }
}

extern "C" void kernel_launch(void* const* d_in, const int* in_sizes, int n_in,
                              void* d_out, int out_size)
{
    const float* x   = (const float*)d_in[0];
    const float* Wih = (const float*)d_in[1];
    const float* Whh = (const float*)d_in[2];
    const float* bih = (const float*)d_in[3];
    const float* bhh = (const float*)d_in[4];
    const float* W1  = (const float*)d_in[5];
    const float* b1  = (const float*)d_in[6];
    const float* W2  = (const float*)d_in[7];
    const float* b2  = (const float*)d_in[8];
    float* out = (float*)d_out;

    xg_kernel<<<NGRID1, NT1>>>(x, Wih, bih, bhh);
    lstm_kernel<<<NGRID2, NTH2>>>(x, Whh, W1, b1, W2, b2, out);
}

// round 16
// speedup vs baseline: 1.3726x; 1.0478x over previous
#include <cuda_runtime.h>

// LSTM B=1024 T=512 F=40 H=50 + MLP head. Round 16.
// lstm_kernel: UNCHANGED from R14 (measured 482us; 4 CTAs/SM domain-filling).
// xg_kernel tuned: TPC=256 (grid 2048, halves per-CTA fixed cost), W_ih
//   staged through SMEM (coalesced) into regs, SMEM buffer reused for the
//   x tile. Same 2-token packed-f32x2 compute loop.

#define BB   1024
#define TT   512
#define FF   40
#define HH   50
#define GG   200
#define RR2  2
#define KZ   52           // h row stride (50 + 2 pad) -> 16B aligned
#define NTH2 128
#define NGRID2 512        // 1024 / RR2

#define NT1  128
#define TPC  256
#define NGRID1 ((BB * TT) / TPC)   // 2048

__device__ float g_xg[(size_t)BB * TT * GG];   // 420 MB scratch (.bss)

__device__ __forceinline__ unsigned long long pk2(float lo, float hi) {
    unsigned long long r;
    asm("mov.b64 %0, {%1, %2};" : "=l"(r) : "f"(lo), "f"(hi));
    return r;
}
__device__ __forceinline__ void upk2(unsigned long long v, float& lo, float& hi) {
    asm("mov.b64 {%0, %1}, %2;" : "=f"(lo), "=f"(hi) : "l"(v));
}
__device__ __forceinline__ unsigned long long f2fma(unsigned long long a,
                                                   unsigned long long b,
                                                   unsigned long long c) {
    unsigned long long d;
    asm("fma.rn.f32x2 %0, %1, %2, %3;" : "=l"(d) : "l"(a), "l"(b), "l"(c));
    return d;
}
__device__ __forceinline__ float tanh_f(float x) {
    float y;
    asm("tanh.approx.f32 %0, %1;" : "=f"(y) : "f"(x));
    return y;
}
__device__ __forceinline__ float sig_f(float x) {
    return fmaf(0.5f, tanh_f(0.5f * x), 0.5f);
}

// ================= kernel 1: xg precompute (tuned) =================
__global__ __launch_bounds__(NT1, 4)
void xg_kernel(const float* __restrict__ x,   const float* __restrict__ Wih,
               const float* __restrict__ bih, const float* __restrict__ bhh)
{
    // 40KB buffer: holds W_ih (8000 floats) first, then the x tile (10240).
    __shared__ __align__(16) float sBuf[TPC * FF];

    const int tid = threadIdx.x;
    const long tok0 = (long)blockIdx.x * TPC;

    // ---- stage W_ih coalesced: 2000 float4 ----
    const float4* __restrict__ wsrc = (const float4*)Wih;
    #pragma unroll
    for (int i = tid; i < GG * FF / 4; i += NT1)
        ((float4*)sBuf)[i] = wsrc[i];
    __syncthreads();

    // ---- copy this thread's two gate rows to registers (vector LDS) ----
    const int j0 = 2 * tid;
    unsigned long long w[40];
    float bsA = 0.f, bsB = 0.f;
    if (tid < 100) {
        const ulonglong2* __restrict__ r0 = (const ulonglong2*)(sBuf + j0 * FF);
        const ulonglong2* __restrict__ r1 = (const ulonglong2*)(sBuf + (j0 + 1) * FF);
        #pragma unroll
        for (int i = 0; i < 10; ++i) {
            ulonglong2 v0 = r0[i];
            ulonglong2 v1 = r1[i];
            w[2 * i]          = v0.x;  w[2 * i + 1]      = v0.y;
            w[20 + 2 * i]     = v1.x;  w[20 + 2 * i + 1] = v1.y;
        }
        bsA = bih[j0]     + bhh[j0];
        bsB = bih[j0 + 1] + bhh[j0 + 1];
    }
    __syncthreads();                       // W reads done before overwrite

    // ---- stage x tile coalesced: 2560 float4 ----
    const float4* __restrict__ src = (const float4*)(x + tok0 * FF);
    #pragma unroll
    for (int i = tid; i < TPC * FF / 4; i += NT1)
        ((float4*)sBuf)[i] = src[i];
    __syncthreads();

    // ---- compute: 2 gates x TPC tokens, 2-token unroll ----
    if (tid < 100) {
        #pragma unroll 1
        for (int tt = 0; tt < TPC; tt += 2) {
            const ulonglong2* __restrict__ xz0 = (const ulonglong2*)(sBuf + tt * FF);
            const ulonglong2* __restrict__ xz1 = (const ulonglong2*)(sBuf + (tt + 1) * FF);
            unsigned long long aA0 = pk2(bsA, 0.f), aB0 = pk2(bsB, 0.f);
            unsigned long long aA1 = pk2(bsA, 0.f), aB1 = pk2(bsB, 0.f);
            #pragma unroll
            for (int i = 0; i < 10; ++i) {
                ulonglong2 z0 = xz0[i];
                ulonglong2 z1 = xz1[i];
                unsigned long long wA0 = w[2 * i],      wA1 = w[2 * i + 1];
                unsigned long long wB0 = w[20 + 2 * i], wB1 = w[20 + 2 * i + 1];
                aA0 = f2fma(wA0, z0.x, aA0); aA0 = f2fma(wA1, z0.y, aA0);
                aB0 = f2fma(wB0, z0.x, aB0); aB0 = f2fma(wB1, z0.y, aB0);
                aA1 = f2fma(wA0, z1.x, aA1); aA1 = f2fma(wA1, z1.y, aA1);
                aB1 = f2fma(wB0, z1.x, aB1); aB1 = f2fma(wB1, z1.y, aB1);
            }
            float lo, hi, vA, vB;
            upk2(aA0, lo, hi); vA = lo + hi;
            upk2(aB0, lo, hi); vB = lo + hi;
            *(float2*)(g_xg + (tok0 + tt) * GG + j0)     = make_float2(vA, vB);
            upk2(aA1, lo, hi); vA = lo + hi;
            upk2(aB1, lo, hi); vB = lo + hi;
            *(float2*)(g_xg + (tok0 + tt + 1) * GG + j0) = make_float2(vA, vB);
        }
    }
}

// ================= kernel 2: recurrence (UNCHANGED from R14) =================
__global__ __launch_bounds__(NTH2, 4)
void lstm_kernel(const float* __restrict__ x,  const float* __restrict__ Whh,
                 const float* __restrict__ W1, const float* __restrict__ b1,
                 const float* __restrict__ W2, const float* __restrict__ b2,
                 float* __restrict__ out)
{
    __shared__ __align__(16) float sZ[RR2][KZ];   // h (+2 pad) per row
    __shared__ __align__(16) float sG[RR2][GG];   // pre-activation gates
    __shared__ __align__(16) float sH[RR2 * 10];  // head scratch

    const int tid  = threadIdx.x;
    const int wid  = tid >> 5;
    const int lane = tid & 31;
    const int b0   = blockIdx.x * RR2;

    for (int i = tid; i < RR2 * KZ; i += NTH2) ((float*)sZ)[i] = 0.0f;

    // compute role: slot s = 25*wid + lane (lane<25) -> gates 2s, 2s+1
    const bool comp = (lane < 25);
    const int s  = wid * 25 + lane;
    const int j0 = 2 * s;

    // W_hh rows j0 and j0+1: 25 packed f32x2 each (K=50 exact)
    unsigned long long w0[25], w1[25];
    #pragma unroll
    for (int k = 0; k < 25; ++k) {
        w0[k] = comp ? pk2(Whh[j0 * HH + 2 * k],       Whh[j0 * HH + 2 * k + 1])       : 0ull;
        w1[k] = comp ? pk2(Whh[(j0 + 1) * HH + 2 * k], Whh[(j0 + 1) * HH + 2 * k + 1]) : 0ull;
    }

    // cell role: s -> (cr = s/50, cu = s%50); c0[:,0] = 1
    const int cr = s / HH;
    const int cu = s - cr * HH;
    float creg = (comp && cu == 0) ? 1.0f : 0.0f;

    // xg streams (float2 per row), load t=0
    const float* __restrict__ pA = g_xg + ((long)(b0 + 0) * TT) * GG + j0;
    const float* __restrict__ pB = g_xg + ((long)(b0 + 1) * TT) * GG + j0;
    float2 xg0 = make_float2(0.f, 0.f), xg1 = xg0;
    if (comp) { xg0 = *(const float2*)pA; xg1 = *(const float2*)pB; }
    __syncthreads();

    for (int t = 0; t < TT; ++t) {
        float2 nx0 = make_float2(0.f, 0.f), nx1 = nx0;
        if (comp) {
            if ((t + 1) < TT) {                    // prefetch xg[t+1]
                nx0 = *(const float2*)(pA + (t + 1) * GG);
                nx1 = *(const float2*)(pB + (t + 1) * GG);
            }
            unsigned long long a00 = pk2(xg0.x, 0.f);
            unsigned long long a10 = pk2(xg0.y, 0.f);
            unsigned long long a01 = pk2(xg1.x, 0.f);
            unsigned long long a11 = pk2(xg1.y, 0.f);
            const ulonglong2* __restrict__ z0b = (const ulonglong2*)&sZ[0][0];
            const ulonglong2* __restrict__ z1b = (const ulonglong2*)&sZ[1][0];
            #pragma unroll
            for (int i = 0; i < 12; ++i) {         // k = 0..47
                ulonglong2 z0 = z0b[i];
                ulonglong2 z1 = z1b[i];
                unsigned long long wa0 = w0[2 * i], wb0 = w0[2 * i + 1];
                unsigned long long wa1 = w1[2 * i], wb1 = w1[2 * i + 1];
                a00 = f2fma(wa0, z0.x, a00); a00 = f2fma(wb0, z0.y, a00);
                a10 = f2fma(wa1, z0.x, a10); a10 = f2fma(wb1, z0.y, a10);
                a01 = f2fma(wa0, z1.x, a01); a01 = f2fma(wb0, z1.y, a01);
                a11 = f2fma(wa1, z1.x, a11); a11 = f2fma(wb1, z1.y, a11);
            }
            {   // tail k = 48,49
                unsigned long long zt0 = *(const unsigned long long*)&sZ[0][48];
                unsigned long long zt1 = *(const unsigned long long*)&sZ[1][48];
                a00 = f2fma(w0[24], zt0, a00);
                a10 = f2fma(w1[24], zt0, a10);
                a01 = f2fma(w0[24], zt1, a01);
                a11 = f2fma(w1[24], zt1, a11);
            }
            float lo, hi, g0v, g1v;
            upk2(a00, lo, hi); g0v = lo + hi;
            upk2(a10, lo, hi); g1v = lo + hi;
            *(float2*)&sG[0][j0] = make_float2(g0v, g1v);
            upk2(a01, lo, hi); g0v = lo + hi;
            upk2(a11, lo, hi); g1v = lo + hi;
            *(float2*)&sG[1][j0] = make_float2(g0v, g1v);
        }
        __syncthreads();

        if (comp) {
            float gi = sG[cr][         cu];
            float gf = sG[cr][    HH + cu];
            float gc = sG[cr][2 * HH + cu];
            float go = sG[cr][3 * HH + cu];
            float si = sig_f(gi);
            float sf = sig_f(gf);
            float tg = tanh_f(gc);
            float so = sig_f(go);
            creg = fmaf(sf, creg, si * tg);
            sZ[cr][cu] = so * tanh_f(creg);
        }
        __syncthreads();

        xg0 = nx0; xg1 = nx1;
    }

    // ================= MLP head =================
    if (tid < RR2 * 10) {
        int r = tid / 10, m = tid - (tid / 10) * 10;
        float sacc = b1[m];
        #pragma unroll
        for (int u = 0; u < HH; ++u)
            sacc = fmaf(sZ[r][u], W1[m * HH + u], sacc);
        sH[tid] = fmaxf(sacc, 0.0f);
    }
    __syncthreads();

    if (tid < RR2) {
        float o = b2[0];
        #pragma unroll
        for (int m = 0; m < 10; ++m)
            o = fmaf(sH[tid * 10 + m], W2[m], o);
        out[b0 + tid] = o + x[((long)(b0 + tid) * TT + (TT - 1)) * FF + 0];
    }
}

extern "C" void kernel_launch(void* const* d_in, const int* in_sizes, int n_in,
                              void* d_out, int out_size)
{
    const float* x   = (const float*)d_in[0];
    const float* Wih = (const float*)d_in[1];
    const float* Whh = (const float*)d_in[2];
    const float* bih = (const float*)d_in[3];
    const float* bhh = (const float*)d_in[4];
    const float* W1  = (const float*)d_in[5];
    const float* b1  = (const float*)d_in[6];
    const float* W2  = (const float*)d_in[7];
    const float* b2  = (const float*)d_in[8];
    float* out = (float*)d_out;

    xg_kernel<<<NGRID1, NT1>>>(x, Wih, bih, bhh);
    lstm_kernel<<<NGRID2, NTH2>>>(x, Whh, W1, b1, W2, b2, out);
}